// round 17
// baseline (speedup 1.0000x reference)
#include <cuda_runtime.h>
#include <cuda_fp16.h>
#include <stdint.h>

constexpr int B  = 2;
constexpr int S  = 2048;
constexpr int D  = 1024;
constexpr int H  = 16;
constexpr int HD = 64;
constexpr int M  = B * S;   // 4096

// Scratch (device globals — no allocation allowed)
__device__ __half g_qh[(size_t)B * H * S * HD];
__device__ __half g_kh[(size_t)B * H * S * HD];
__device__ __half g_vh[(size_t)B * H * S * HD];
__device__ __half g_attnh[(size_t)B * S * D];
__device__ __half g_xh[(size_t)M * D];          // fp16 x
__device__ __half g_wh[4 * (size_t)D * D];      // fp16 Wq,Wk,Wv,Wp

__device__ __forceinline__ uint32_t pack_h2(float a, float b) {
    __half2 h = __floats2half2_rn(a, b);
    return *(uint32_t*)&h;
}

__device__ __forceinline__ void mma16(float* c,
                                      uint32_t a0, uint32_t a1, uint32_t a2, uint32_t a3,
                                      uint32_t b0, uint32_t b1) {
    asm volatile(
        "mma.sync.aligned.m16n8k16.row.col.f32.f16.f16.f32 "
        "{%0,%1,%2,%3},{%4,%5,%6,%7},{%8,%9},{%0,%1,%2,%3};"
        : "+f"(c[0]), "+f"(c[1]), "+f"(c[2]), "+f"(c[3])
        : "r"(a0), "r"(a1), "r"(a2), "r"(a3), "r"(b0), "r"(b1));
}

__device__ __forceinline__ uint4 ldsm4(uint32_t addr) {
    uint4 r;
    asm volatile("ldmatrix.sync.aligned.m8n8.x4.shared.b16 {%0,%1,%2,%3}, [%4];"
                 : "=r"(r.x), "=r"(r.y), "=r"(r.z), "=r"(r.w) : "r"(addr));
    return r;
}
__device__ __forceinline__ uint4 ldsm4t(uint32_t addr) {
    uint4 r;
    asm volatile("ldmatrix.sync.aligned.m8n8.x4.trans.shared.b16 {%0,%1,%2,%3}, [%4];"
                 : "=r"(r.x), "=r"(r.y), "=r"(r.z), "=r"(r.w) : "r"(addr));
    return r;
}

// two exponentials (base-2) in one MUFU op on packed halves
__device__ __forceinline__ uint32_t ex2_h2(float a, float b) {
    __half2 h = __floats2half2_rn(a, b);
    uint32_t u = *(uint32_t*)&h;
    asm("ex2.approx.f16x2 %0, %0;" : "+r"(u));
    return u;
}

__device__ __forceinline__ void cpa16(uint32_t dst, const void* src) {
    asm volatile("cp.async.cg.shared.global [%0], [%1], 16;" :: "r"(dst), "l"(src));
}
__device__ __forceinline__ void cpcommit() { asm volatile("cp.async.commit_group;"); }
template <int N>
__device__ __forceinline__ void cpwait() { asm volatile("cp.async.wait_group %0;" :: "n"(N)); }

// ---------------------------------------------------------------------------
// fp16 convert pass: x and the 4 weight matrices (rounding happens HERE)
// ---------------------------------------------------------------------------
__global__ __launch_bounds__(256)
void h_cvt(const float* __restrict__ x,  const float* __restrict__ wq,
           const float* __restrict__ wk, const float* __restrict__ wv,
           const float* __restrict__ wp,
           __half* __restrict__ xo, __half* __restrict__ qo,
           __half* __restrict__ ko, __half* __restrict__ vo, __half* __restrict__ po)
{
    const float* s; __half* d; int n;
    switch (blockIdx.y) {
        case 0: s = x;  d = xo; n = M * D; break;
        case 1: s = wq; d = qo; n = D * D; break;
        case 2: s = wk; d = ko; n = D * D; break;
        case 3: s = wv; d = vo; n = D * D; break;
        default: s = wp; d = po; n = D * D; break;
    }
    for (int i = (blockIdx.x * 256 + threadIdx.x) * 4; i < n; i += 512 * 256 * 4) {
        const float4 v = *(const float4*)(s + i);
        uint2 o;
        o.x = pack_h2(v.x, v.y);
        o.y = pack_h2(v.z, v.w);
        *(uint2*)(d + i) = o;
    }
}

// ---------------------------------------------------------------------------
// FP16 GEMM (unchanged from R16): C = A * W^T + bias, fp32 accumulate.
// Block 128x128, BK=32 halves, 8 warps, warp tile 64x32, cp.async 4-stage.
// MODE 0: fp32 out. MODE 2: QKV fused (z), fp16 scatter; Q scaled 0.125.
// ---------------------------------------------------------------------------
template <int MODE>
__global__ __launch_bounds__(256, 2)
void gemm_h(const __half* __restrict__ A,
            const __half* __restrict__ W0, const float* __restrict__ b0_,
            const __half* __restrict__ W1, const float* __restrict__ b1_,
            const __half* __restrict__ W2, const float* __restrict__ b2_,
            float* __restrict__ Cf,
            __half* __restrict__ Ch0, __half* __restrict__ Ch1, __half* __restrict__ Ch2)
{
    constexpr int K = 1024;
    constexpr int N = 1024;
    constexpr int NKB = 32;   // BK = 32 halves

    const __half* W; const float* bias; __half* Ch = nullptr; int z = 0;
    if (MODE != 2) { W = W0; bias = b0_; }
    else {
        z    = blockIdx.z;
        W    = (z == 0) ? W0 : (z == 1) ? W1 : W2;
        bias = (z == 0) ? b0_ : (z == 1) ? b1_ : b2_;
        Ch   = (z == 0) ? Ch0 : (z == 1) ? Ch1 : Ch2;
    }

    extern __shared__ __align__(16) uint32_t smg[];
    const uint32_t sbase = (uint32_t)__cvta_generic_to_shared(smg);

    const int t    = threadIdx.x;
    const int lane = t & 31;
    const int warp = t >> 5;
    const int gid  = lane >> 2;
    const int tig  = lane & 3;
    const int wm   = warp >> 2;
    const int wn   = warp & 3;
    const int bm   = blockIdx.y * 128;
    const int bn   = blockIdx.x * 128;

    const int srow = t >> 2;
    const int sg   = t & 3;
    const __half* sa0 = A + (size_t)(bm + srow) * K + sg * 8;
    const __half* sw0 = W + (size_t)(bn + srow) * K + sg * 8;
    const uint32_t dsw = (uint32_t)(srow * 64 + ((sg ^ ((srow >> 1) & 3)) << 4));

    uint32_t relA[4], relB[2];
    {
        const int hi = lane >> 4;
#pragma unroll
        for (int mt = 0; mt < 4; mt++) {
            const int row = wm * 64 + mt * 16 + (lane & 7) + (lane & 8);
            relA[mt] = row * 64 + (uint32_t)((hi ^ ((row >> 1) & 3)) << 4);
        }
#pragma unroll
        for (int n2 = 0; n2 < 2; n2++) {
            const int row = wn * 32 + n2 * 16 + (lane & 7) + (lane & 8);
            relB[n2] = 8192u + row * 64 + (uint32_t)((hi ^ ((row >> 1) & 3)) << 4);
        }
    }

#define GISSUE(kb, st)                                            \
    {                                                             \
        const uint32_t dd = sbase + (uint32_t)(st) * 16384u + dsw;\
        const __half* a = sa0 + (kb) * 32;                        \
        const __half* w = sw0 + (kb) * 32;                        \
        cpa16(dd,          a);                                    \
        cpa16(dd + 4096,   a + (size_t)64 * K);                   \
        cpa16(dd + 8192,   w);                                    \
        cpa16(dd + 12288,  w + (size_t)64 * K);                   \
    }

    float acc[4][4][4];
#pragma unroll
    for (int i = 0; i < 4; i++)
#pragma unroll
        for (int j = 0; j < 4; j++)
#pragma unroll
            for (int l = 0; l < 4; l++) acc[i][j][l] = 0.f;

    GISSUE(0, 0); cpcommit();
    GISSUE(1, 1); cpcommit();
    GISSUE(2, 2); cpcommit();

    for (int kb = 0; kb < NKB; kb++) {
        cpwait<2>();
        __syncthreads();
        if (kb + 3 < NKB) GISSUE(kb + 3, (kb + 3) & 3);
        cpcommit();

        const uint32_t sbk = sbase + (uint32_t)((kb & 3) << 14);
#pragma unroll
        for (int ks = 0; ks < 2; ks++) {
            const uint32_t kx = (uint32_t)(ks << 5);
            uint4 af[4];
#pragma unroll
            for (int mt = 0; mt < 4; mt++)
                af[mt] = ldsm4(sbk + (relA[mt] ^ kx));
            const uint4 bq0 = ldsm4(sbk + (relB[0] ^ kx));
            const uint4 bq1 = ldsm4(sbk + (relB[1] ^ kx));
#pragma unroll
            for (int mt = 0; mt < 4; mt++) {
                mma16(acc[mt][0], af[mt].x, af[mt].y, af[mt].z, af[mt].w, bq0.x, bq0.z);
                mma16(acc[mt][1], af[mt].x, af[mt].y, af[mt].z, af[mt].w, bq0.y, bq0.w);
                mma16(acc[mt][2], af[mt].x, af[mt].y, af[mt].z, af[mt].w, bq1.x, bq1.z);
                mma16(acc[mt][3], af[mt].x, af[mt].y, af[mt].z, af[mt].w, bq1.y, bq1.w);
            }
        }
    }
#undef GISSUE

    // ---- epilogue ----
    const float qs = (MODE == 2 && z == 0) ? 0.125f : 1.0f;
#pragma unroll
    for (int mt = 0; mt < 4; mt++) {
        const int r1 = bm + wm * 64 + mt * 16 + gid;
        const int r2 = r1 + 8;
#pragma unroll
        for (int nt = 0; nt < 4; nt++) {
            const int n = bn + wn * 32 + nt * 8 + 2 * tig;
            const float bx = __ldg(&bias[n]), by = __ldg(&bias[n + 1]);
            if (MODE == 0) {
                *(float2*)&Cf[(size_t)r1 * N + n] =
                    make_float2(acc[mt][nt][0] + bx, acc[mt][nt][1] + by);
                *(float2*)&Cf[(size_t)r2 * N + n] =
                    make_float2(acc[mt][nt][2] + bx, acc[mt][nt][3] + by);
            } else {
                const uint32_t v1 = pack_h2((acc[mt][nt][0] + bx) * qs,
                                            (acc[mt][nt][1] + by) * qs);
                const uint32_t v2 = pack_h2((acc[mt][nt][2] + bx) * qs,
                                            (acc[mt][nt][3] + by) * qs);
                const int hh = n >> 6, ee = n & 63;
                const int b1r = r1 >> 11, s1r = r1 & (S - 1);
                const int b2r = r2 >> 11, s2r = r2 & (S - 1);
                *(uint32_t*)&Ch[(((size_t)b1r * H + hh) * S + s1r) * HD + ee] = v1;
                *(uint32_t*)&Ch[(((size_t)b2r * H + hh) * S + s2r) * HD + ee] = v2;
            }
        }
    }
}

// ---------------------------------------------------------------------------
// FP16 flash attention: 128-row Q tiles, 256 threads (8 warps; each warp's
// 16-row program is bit-identical to R16). KV staged ONCE per 128 Q rows
// (traffic halved). ex2.approx.f16x2 softmax.
// Smem bytes: K0 @0, K1 @8192, V0 @16384, V1 @24576, Q @32768 (16KB),
// P @49152 (16KB). Total 65536 B.
// ---------------------------------------------------------------------------
__global__ __launch_bounds__(256)
void attn_h(const __half* __restrict__ q,
            const __half* __restrict__ k,
            const __half* __restrict__ v,
            __half* __restrict__ out)
{
    extern __shared__ __align__(16) uint32_t sma[];
    const uint32_t sb = (uint32_t)__cvta_generic_to_shared(sma);

    const int t    = threadIdx.x;
    const int lane = t & 31;
    const int warp = t >> 5;          // 0..7
    const int gid  = lane >> 2;
    const int tig  = lane & 3;
    const int rm   = warp * 16;

    const int hb = blockIdx.y, bb = blockIdx.z;
    const int m0 = blockIdx.x * 128;
    const size_t base = ((size_t)bb * H + hb) * S * HD;
    const __half* qb  = q + base + (size_t)m0 * HD;
    const __half* kb_ = k + base;
    const __half* vb_ = v + base;

    // staging: 256 threads; chunk = t -> row cr (0..31), 16B chunk cg (0..7)
    const int cr = t >> 3;
    const int cg = t & 7;

    // ---- issue Q (128 rows, group 0) ----
#pragma unroll
    for (int i = 0; i < 4; i++) {
        const int row = i * 32 + cr;
        cpa16(sb + 32768u + row * 128 + (uint32_t)((cg ^ (row & 7)) << 4),
              qb + row * 64 + cg * 8);
    }
    cpcommit();

#define KV_ISSUE(n0, buf)                                                        \
    {                                                                            \
        const __half* kp = kb_ + (size_t)(n0) * HD;                              \
        const __half* vp = vb_ + (size_t)(n0) * HD;                              \
        _Pragma("unroll")                                                        \
        for (int i = 0; i < 2; i++) {                                            \
            const int row = i * 32 + cr;                                         \
            const uint32_t sw = (uint32_t)((cg ^ (row & 7)) << 4);               \
            cpa16(sb + (uint32_t)(buf) * 8192u + row * 128 + sw,                 \
                  kp + row * 64 + cg * 8);                                       \
            cpa16(sb + 16384u + (uint32_t)(buf) * 8192u + row * 128 + sw,        \
                  vp + row * 64 + cg * 8);                                       \
        }                                                                        \
    }

    KV_ISSUE(0, 0);  cpcommit();
    KV_ISSUE(64, 1); cpcommit();

    // ---- fragment addresses ----
    uint32_t relK[4], relQ, relP, relV;
    {
        const int hi = lane >> 4;
#pragma unroll
        for (int n2 = 0; n2 < 4; n2++) {
            const int row = n2 * 16 + (lane & 7) + (lane & 8);
            relK[n2] = row * 128 + (uint32_t)((hi ^ (row & 7)) << 4);
        }
        const int rowq = rm + (lane & 7) + (lane & 8);
        relQ = 32768u + rowq * 128 + (uint32_t)((hi ^ (rowq & 7)) << 4);
        relP = 49152u + rowq * 128 + (uint32_t)((hi ^ (rowq & 7)) << 4);
        const int vrow = lane & 15;
        relV = 16384u + vrow * 128 + (uint32_t)((hi ^ (lane & 7)) << 4);
    }

    cpwait<2>();
    __syncthreads();
    uint4 qf[4];
#pragma unroll
    for (int ks = 0; ks < 4; ks++)
        qf[ks] = ldsm4(sb + (relQ ^ (uint32_t)(ks << 5)));

    constexpr float L2E = 1.4426950408889634f;
    float m1 = -1e30f, m2 = -1e30f, l1 = 0.f, l2 = 0.f;
    float o[8][4];
#pragma unroll
    for (int nt = 0; nt < 8; nt++)
#pragma unroll
        for (int j = 0; j < 4; j++) o[nt][j] = 0.f;

    for (int kt = 0; kt < 32; kt++) {
        cpwait<1>();
        __syncthreads();
        const uint32_t kbase = sb + (uint32_t)((kt & 1) << 13);
        const uint32_t voff  = (uint32_t)((kt & 1) << 13);

        // ---- scores = Q . K^T ----
        float sc[8][4];
#pragma unroll
        for (int nt = 0; nt < 8; nt++)
#pragma unroll
            for (int j = 0; j < 4; j++) sc[nt][j] = 0.f;
#pragma unroll
        for (int ks = 0; ks < 4; ks++) {
            const uint32_t kx = (uint32_t)(ks << 5);
#pragma unroll
            for (int n2 = 0; n2 < 4; n2++) {
                const uint4 bf = ldsm4(kbase + (relK[n2] ^ kx));
                mma16(sc[2 * n2],     qf[ks].x, qf[ks].y, qf[ks].z, qf[ks].w, bf.x, bf.z);
                mma16(sc[2 * n2 + 1], qf[ks].x, qf[ks].y, qf[ks].z, qf[ks].w, bf.y, bf.w);
            }
        }

        // ---- online softmax: max in fp32, exp via ex2.approx.f16x2 ----
        float mx1 = -1e30f, mx2 = -1e30f;
#pragma unroll
        for (int nt = 0; nt < 8; nt++) {
            mx1 = fmaxf(mx1, fmaxf(sc[nt][0], sc[nt][1]));
            mx2 = fmaxf(mx2, fmaxf(sc[nt][2], sc[nt][3]));
        }
        mx1 = fmaxf(mx1, __shfl_xor_sync(0xffffffffu, mx1, 1));
        mx1 = fmaxf(mx1, __shfl_xor_sync(0xffffffffu, mx1, 2));
        mx2 = fmaxf(mx2, __shfl_xor_sync(0xffffffffu, mx2, 1));
        mx2 = fmaxf(mx2, __shfl_xor_sync(0xffffffffu, mx2, 2));
        const float M1 = fmaxf(m1, mx1);
        const float M2 = fmaxf(m2, mx2);

        uint32_t ph1[8], ph2[8];
        float s1 = 0.f, s2 = 0.f;
#pragma unroll
        for (int nt = 0; nt < 8; nt++) {
            ph1[nt] = ex2_h2((sc[nt][0] - M1) * L2E, (sc[nt][1] - M1) * L2E);
            ph2[nt] = ex2_h2((sc[nt][2] - M2) * L2E, (sc[nt][3] - M2) * L2E);
            const float2 f1 = __half22float2(*(__half2*)&ph1[nt]);
            const float2 f2 = __half22float2(*(__half2*)&ph2[nt]);
            s1 += f1.x + f1.y;
            s2 += f2.x + f2.y;
        }
        s1 += __shfl_xor_sync(0xffffffffu, s1, 1);
        s1 += __shfl_xor_sync(0xffffffffu, s1, 2);
        s2 += __shfl_xor_sync(0xffffffffu, s2, 1);
        s2 += __shfl_xor_sync(0xffffffffu, s2, 2);

        const float c1 = __expf(m1 - M1);
        const float c2 = __expf(m2 - M2);
        l1 = l1 * c1 + s1;
        l2 = l2 * c2 + s2;
        m1 = M1; m2 = M2;
#pragma unroll
        for (int nt = 0; nt < 8; nt++) {
            o[nt][0] *= c1; o[nt][1] *= c1;
            o[nt][2] *= c2; o[nt][3] *= c2;
        }

        // ---- P -> smem (already f16x2), warp-private rows ----
        {
            const int row1 = rm + gid;
            const int row2 = row1 + 8;
#pragma unroll
            for (int nt = 0; nt < 8; nt++) {
                const uint32_t o1 = 49152u + row1 * 128 +
                                    (uint32_t)(((nt ^ (row1 & 7)) << 4) + tig * 4);
                const uint32_t o2 = 49152u + row2 * 128 +
                                    (uint32_t)(((nt ^ (row2 & 7)) << 4) + tig * 4);
                *(uint32_t*)((char*)sma + o1) = ph1[nt];
                *(uint32_t*)((char*)sma + o2) = ph2[nt];
            }
        }
        __syncwarp();

        // ---- O += P . V  (P via ldsm, V via ldsm.trans) ----
#pragma unroll
        for (int ksp = 0; ksp < 4; ksp++) {
            const uint4 pf = ldsm4(sb + (relP ^ (uint32_t)(ksp << 5)));
            const uint32_t vk = relV + voff + (uint32_t)(ksp * 2048);
#pragma unroll
            for (int n2 = 0; n2 < 4; n2++) {
                const uint4 vf = ldsm4t(sb + (vk ^ (uint32_t)(n2 << 5)));
                mma16(o[2 * n2],     pf.x, pf.y, pf.z, pf.w, vf.x, vf.y);
                mma16(o[2 * n2 + 1], pf.x, pf.y, pf.z, pf.w, vf.z, vf.w);
            }
        }

        __syncthreads();
        if (kt + 2 < 32) KV_ISSUE((kt + 2) * 64, kt & 1);
        cpcommit();
    }
#undef KV_ISSUE

    // ---- epilogue: normalize, fp16, write concat-head layout ----
    const float i1 = 1.f / l1;
    const float i2 = 1.f / l2;
    const int s1r = m0 + rm + gid;
    const int s2r = s1r + 8;
#pragma unroll
    for (int nt = 0; nt < 8; nt++) {
        const int n = nt * 8 + 2 * tig;
        *(uint32_t*)&out[((size_t)bb * S + s1r) * D + hb * HD + n] =
            pack_h2(o[nt][0] * i1, o[nt][1] * i1);
        *(uint32_t*)&out[((size_t)bb * S + s2r) * D + hb * HD + n] =
            pack_h2(o[nt][2] * i2, o[nt][3] * i2);
    }
}

// ---------------------------------------------------------------------------
// Launch
// ---------------------------------------------------------------------------
extern "C" void kernel_launch(void* const* d_in, const int* in_sizes, int n_in,
                              void* d_out, int out_size)
{
    const float* x  = (const float*)d_in[0];
    const float* Wq = (const float*)d_in[1];
    const float* bq = (const float*)d_in[2];
    const float* Wk = (const float*)d_in[3];
    const float* bk = (const float*)d_in[4];
    const float* Wv = (const float*)d_in[5];
    const float* bv = (const float*)d_in[6];
    const float* Wp = (const float*)d_in[7];
    const float* bp = (const float*)d_in[8];
    float* out = (float*)d_out;

    __half *qh, *kh, *vh, *attnh, *xh, *wh;
    cudaGetSymbolAddress((void**)&qh,    g_qh);
    cudaGetSymbolAddress((void**)&kh,    g_kh);
    cudaGetSymbolAddress((void**)&vh,    g_vh);
    cudaGetSymbolAddress((void**)&attnh, g_attnh);
    cudaGetSymbolAddress((void**)&xh,    g_xh);
    cudaGetSymbolAddress((void**)&wh,    g_wh);
    __half* wqh = wh;
    __half* wkh = wh + (size_t)D * D;
    __half* wvh = wh + 2 * (size_t)D * D;
    __half* wph = wh + 3 * (size_t)D * D;

    const int smem_gemm = 4 * 16384;   // 65536
    const int smem_attn = 65536;

    cudaFuncSetAttribute(gemm_h<2>, cudaFuncAttributeMaxDynamicSharedMemorySize, smem_gemm);
    cudaFuncSetAttribute(gemm_h<0>, cudaFuncAttributeMaxDynamicSharedMemorySize, smem_gemm);
    cudaFuncSetAttribute(attn_h,    cudaFuncAttributeMaxDynamicSharedMemorySize, smem_attn);

    h_cvt<<<dim3(512, 5), 256>>>(x, Wq, Wk, Wv, Wp, xh, wqh, wkh, wvh, wph);

    gemm_h<2><<<dim3(D / 128, M / 128, 3), 256, smem_gemm>>>(
        xh, wqh, bq, wkh, bk, wvh, bv, nullptr, qh, kh, vh);

    attn_h<<<dim3(S / 128, H, B), 256, smem_attn>>>(qh, kh, vh, attnh);

    gemm_h<0><<<dim3(D / 128, M / 128), 256, smem_gemm>>>(
        attnh, wph, bp, nullptr, nullptr, nullptr, nullptr, out, nullptr, nullptr, nullptr);
}